// round 2
// baseline (speedup 1.0000x reference)
#include <cuda_runtime.h>
#include <math.h>

// Problem constants
#define BSZ 8
#define CCH 256
#define NSP 1024           // H*W
#define NHH 4
#define DKD 64
#define CNT (CCH*NSP)      // 262144 elements per batch for GroupNorm

// -------- scratch (no allocations allowed) --------
__device__ float g_sums1[2*BSZ];                 // GN1: per-batch sum, sumsq
__device__ float g_sums2[2*BSZ];                 // GN2
__device__ float g_qkv [(size_t)BSZ*3*CCH*NSP];  // 24 MB
__device__ float g_attn[(size_t)BSZ*CCH*NSP];    // 8 MB
__device__ float g_x2  [(size_t)BSZ*CCH*NSP];    // 8 MB
__device__ float g_h1  [(size_t)BSZ*4*CCH*NSP];  // 32 MB

// -------- helpers --------
__device__ __forceinline__ void block_reduce2(float& s, float& s2) {
    #pragma unroll
    for (int o = 16; o; o >>= 1) {
        s  += __shfl_xor_sync(0xffffffffu, s,  o);
        s2 += __shfl_xor_sync(0xffffffffu, s2, o);
    }
    __shared__ float sh0[8], sh1[8];
    int w = threadIdx.x >> 5, l = threadIdx.x & 31;
    if (l == 0) { sh0[w] = s; sh1[w] = s2; }
    __syncthreads();
    if (w == 0) {
        s  = (l < 8) ? sh0[l] : 0.f;
        s2 = (l < 8) ? sh1[l] : 0.f;
        #pragma unroll
        for (int o = 4; o; o >>= 1) {
            s  += __shfl_xor_sync(0xffffffffu, s,  o);
            s2 += __shfl_xor_sync(0xffffffffu, s2, o);
        }
    }
}

__global__ void zero_stats_kernel() {
    int t = threadIdx.x;
    if (t < 2*BSZ) { g_sums1[t] = 0.f; g_sums2[t] = 0.f; }
}

// Per-batch sum / sumsq of x. grid (32 chunks, BSZ), 256 threads
__global__ void gn_stats_kernel(const float* __restrict__ x) {
    int b = blockIdx.y;
    const float* xb = x + (size_t)b * CNT;
    int base = blockIdx.x * (CNT / 32);
    float s = 0.f, s2 = 0.f;
    for (int i = threadIdx.x; i < CNT/32; i += 256) {
        float v = xb[base + i];
        s += v; s2 += v*v;
    }
    block_reduce2(s, s2);
    if (threadIdx.x == 0) {
        atomicAdd(&g_sums1[b*2],   s);
        atomicAdd(&g_sums1[b*2+1], s2);
    }
}

// ------------------------------------------------------------------
// Fused GEMM: C[b][m][n] = sum_k A[m][k] * Bin'[b][k][n]
//   NORMSRC: 0 = Bin used raw; 1 = GN with g_sums1; 2 = GN with g_sums2
//   BIAS: += bias[m]; SILU: x*sigmoid(x); RESID: out = resid + gamma*val
//   STATS: accumulate sum/sumsq of final output into g_sums2
// 64x64 tile, BK=16, 256 threads, 4x4 microtile. N fixed = 1024.
// ------------------------------------------------------------------
template<int NORMSRC, bool BIAS, bool SILU, bool RESID, bool STATS>
__global__ void gemm_fused_kernel(const float* __restrict__ A,
                                  const float* __restrict__ Bin,
                                  const float* __restrict__ gw,
                                  const float* __restrict__ gb,
                                  const float* __restrict__ bias,
                                  const float* __restrict__ resid,
                                  const float* __restrict__ gamma,
                                  float* __restrict__ Cout,
                                  int M, int K) {
    const int N = NSP;
    __shared__ float As[16][68];
    __shared__ float Bs[16][68];

    int b  = blockIdx.z;
    int m0 = blockIdx.y * 64, n0 = blockIdx.x * 64;
    int tid = threadIdx.x;
    int tx = tid & 15, ty = tid >> 4;

    float mean = 0.f, rstd = 0.f;
    if (NORMSRC) {
        const float* sums = (NORMSRC == 1) ? g_sums1 : g_sums2;
        float s = sums[b*2], s2 = sums[b*2+1];
        mean = s * (1.0f / CNT);
        float var = s2 * (1.0f / CNT) - mean * mean;
        rstd = rsqrtf(var + 1e-5f);
    }

    const float* Bb = Bin + (size_t)b * K * N;
    float acc[4][4] = {};

    int la_k = tid & 15, la_m = tid >> 4;   // A tile loader coords
    int lb_n = tid & 63, lb_k = tid >> 6;   // B tile loader coords

    for (int k0 = 0; k0 < K; k0 += 16) {
        #pragma unroll
        for (int r = 0; r < 4; r++)
            As[la_k][la_m + 16*r] = A[(size_t)(m0 + la_m + 16*r) * K + k0 + la_k];
        #pragma unroll
        for (int r = 0; r < 4; r++) {
            int k = k0 + lb_k + 4*r;
            float v = Bb[(size_t)k * N + n0 + lb_n];
            if (NORMSRC) v = (v - mean) * rstd * gw[k] + gb[k];
            Bs[lb_k + 4*r][lb_n] = v;
        }
        __syncthreads();
        #pragma unroll
        for (int kk = 0; kk < 16; kk++) {
            float a[4], bb[4];
            *(float4*)a  = *(const float4*)&As[kk][ty*4];
            *(float4*)bb = *(const float4*)&Bs[kk][tx*4];
            #pragma unroll
            for (int i = 0; i < 4; i++)
                #pragma unroll
                for (int j = 0; j < 4; j++)
                    acc[i][j] += a[i] * bb[j];
        }
        __syncthreads();
    }

    float g = RESID ? gamma[0] : 0.f;
    float s1 = 0.f, sq = 0.f;
    #pragma unroll
    for (int i = 0; i < 4; i++) {
        int m = m0 + ty*4 + i;
        float bi = BIAS ? bias[m] : 0.f;
        #pragma unroll
        for (int j = 0; j < 4; j++) {
            int n = n0 + tx*4 + j;
            float v = acc[i][j] + bi;
            if (SILU) v = v / (1.f + expf(-v));
            size_t idx = ((size_t)b * M + m) * N + n;
            if (RESID) v = resid[idx] + g * v;
            Cout[idx] = v;
            if (STATS) { s1 += v; sq += v*v; }
        }
    }
    if (STATS) {
        __syncthreads();
        block_reduce2(s1, sq);
        if (tid == 0) {
            atomicAdd(&g_sums2[b*2],   s1);
            atomicAdd(&g_sums2[b*2+1], sq);
        }
    }
}

// ------------------------------------------------------------------
// Flash attention: one block per (query-tile of 64, head, batch).
// 256 threads (16x16), online softmax, 64-wide K/V tiles.
// ------------------------------------------------------------------
__global__ void attn_kernel(const float* __restrict__ qkv, float* __restrict__ outp) {
    extern __shared__ float sm[];
    float* qs = sm;              // [64][68] q[d][i] (pre-scaled)
    float* ks = qs + 64*68;      // [64][68] k[d][j]  (also reused for output staging)
    float* ps = ks + 64*68;      // [64][68] p[i][j]
    float* vs = ps + 64*68;      // [64][65] v^T[j][d]

    int it = blockIdx.x, h = blockIdx.y, b = blockIdx.z;
    int tid = threadIdx.x, tx = tid & 15, ty = tid >> 4;
    int li = tid & 63, ld = tid >> 6;

    const float* qb = qkv + ((size_t)b*3*CCH +          h*DKD) * NSP + it*64;
    const float* kb = qkv + ((size_t)b*3*CCH +   CCH +  h*DKD) * NSP;
    const float* vb = qkv + ((size_t)b*3*CCH + 2*CCH +  h*DKD) * NSP;

    // load Q tile, pre-scale by 1/sqrt(dk). 256 thr x 16 iters = 64x64 tile.
    #pragma unroll
    for (int r = 0; r < 16; r++) {
        int d = ld + 4*r;
        qs[d*68 + li] = qb[(size_t)d * NSP + li] * 0.125f;
    }

    float m_r[4], l_r[4], acc[4][4];
    #pragma unroll
    for (int u = 0; u < 4; u++) {
        m_r[u] = -1e30f; l_r[u] = 0.f;
        #pragma unroll
        for (int v = 0; v < 4; v++) acc[u][v] = 0.f;
    }

    for (int kt = 0; kt < 16; kt++) {
        __syncthreads();
        #pragma unroll
        for (int r = 0; r < 16; r++) {
            int d = ld + 4*r;
            ks[d*68 + li]  = kb[(size_t)d * NSP + kt*64 + li];
            vs[li*65 + d]  = vb[(size_t)d * NSP + kt*64 + li];
        }
        __syncthreads();

        // scores s[i][j] = sum_d qs[d][i]*ks[d][j]
        float s[4][4] = {};
        #pragma unroll 8
        for (int d = 0; d < 64; d++) {
            float q4[4], k4[4];
            *(float4*)q4 = *(const float4*)&qs[d*68 + ty*4];
            *(float4*)k4 = *(const float4*)&ks[d*68 + tx*4];
            #pragma unroll
            for (int u = 0; u < 4; u++)
                #pragma unroll
                for (int v = 0; v < 4; v++)
                    s[u][v] += q4[u] * k4[v];
        }

        // online softmax per row
        #pragma unroll
        for (int u = 0; u < 4; u++) {
            float mloc = fmaxf(fmaxf(s[u][0], s[u][1]), fmaxf(s[u][2], s[u][3]));
            #pragma unroll
            for (int o = 1; o < 16; o <<= 1)
                mloc = fmaxf(mloc, __shfl_xor_sync(0xffffffffu, mloc, o));
            float mnew  = fmaxf(m_r[u], mloc);
            float alpha = expf(m_r[u] - mnew);
            m_r[u] = mnew;
            float ls = 0.f;
            #pragma unroll
            for (int v = 0; v < 4; v++) {
                s[u][v] = expf(s[u][v] - mnew);
                ls += s[u][v];
            }
            #pragma unroll
            for (int o = 1; o < 16; o <<= 1)
                ls += __shfl_xor_sync(0xffffffffu, ls, o);
            l_r[u] = l_r[u] * alpha + ls;
            #pragma unroll
            for (int v = 0; v < 4; v++) {
                acc[u][v] *= alpha;
                ps[(ty*4 + u)*68 + tx*4 + v] = s[u][v];
            }
        }
        __syncthreads();

        // out[i][d] += sum_j p[i][j] * v[d][j]
        #pragma unroll 8
        for (int j = 0; j < 64; j++) {
            float pv[4], vv[4];
            #pragma unroll
            for (int u = 0; u < 4; u++) pv[u] = ps[(ty*4 + u)*68 + j];
            #pragma unroll
            for (int v = 0; v < 4; v++) vv[v] = vs[j*65 + tx*4 + v];
            #pragma unroll
            for (int u = 0; u < 4; u++)
                #pragma unroll
                for (int v = 0; v < 4; v++)
                    acc[u][v] += pv[u] * vv[v];
        }
    }

    // finalize and stage through smem (ks reused) for coalesced writes
    __syncthreads();
    #pragma unroll
    for (int u = 0; u < 4; u++) {
        float inv = 1.0f / l_r[u];
        #pragma unroll
        for (int v = 0; v < 4; v++)
            ks[(tx*4 + v)*68 + ty*4 + u] = acc[u][v] * inv;   // os[d][i]
    }
    __syncthreads();
    float* ob = outp + ((size_t)b*CCH + h*DKD) * NSP + it*64;
    #pragma unroll
    for (int r = 0; r < 16; r++) {
        int d = ld + 4*r;
        ob[(size_t)d * NSP + li] = ks[d*68 + li];
    }
}

// ------------------------------------------------------------------
extern "C" void kernel_launch(void* const* d_in, const int* in_sizes, int n_in,
                              void* d_out, int out_size) {
    const float* x     = (const float*)d_in[0];
    const float* qkv_w = (const float*)d_in[1];
    const float* uh_w  = (const float*)d_in[2];
    const float* uh_b  = (const float*)d_in[3];
    const float* n1_w  = (const float*)d_in[4];
    const float* n1_b  = (const float*)d_in[5];
    const float* n2_w  = (const float*)d_in[6];
    const float* n2_b  = (const float*)d_in[7];
    const float* f1_w  = (const float*)d_in[8];
    const float* f1_b  = (const float*)d_in[9];
    const float* f2_w  = (const float*)d_in[10];
    const float* f2_b  = (const float*)d_in[11];
    const float* g_at  = (const float*)d_in[12];
    const float* g_ff  = (const float*)d_in[13];
    float* out = (float*)d_out;

    float *qkv_buf, *attn_buf, *x2_buf, *h1_buf;
    cudaGetSymbolAddress((void**)&qkv_buf,  g_qkv);
    cudaGetSymbolAddress((void**)&attn_buf, g_attn);
    cudaGetSymbolAddress((void**)&x2_buf,   g_x2);
    cudaGetSymbolAddress((void**)&h1_buf,   g_h1);

    cudaFuncSetAttribute(attn_kernel,
                         cudaFuncAttributeMaxDynamicSharedMemorySize, 70000);

    // 1) zero stats accumulators
    zero_stats_kernel<<<1, 32>>>();

    // 2) GN1 stats on x
    gn_stats_kernel<<<dim3(32, BSZ), 256>>>(x);

    // 3) qkv = qkv_w @ GN1(x)       [M=768, K=256]
    gemm_fused_kernel<1, false, false, false, false>
        <<<dim3(16, 12, BSZ), 256>>>(qkv_w, x, n1_w, n1_b,
                                     nullptr, nullptr, nullptr, qkv_buf, 3*CCH, CCH);

    // 4) attention
    attn_kernel<<<dim3(16, NHH, BSZ), 256, 70000>>>(qkv_buf, attn_buf);

    // 5) x2 = x + g_attn * (uh_w @ attn + uh_b); also accumulate GN2 stats
    gemm_fused_kernel<0, true, false, true, true>
        <<<dim3(16, 4, BSZ), 256>>>(uh_w, attn_buf, nullptr, nullptr,
                                    uh_b, x, g_at, x2_buf, CCH, CCH);

    // 6) h1 = silu(f1_w @ GN2(x2) + f1_b)   [M=1024, K=256]
    gemm_fused_kernel<2, true, true, false, false>
        <<<dim3(16, 16, BSZ), 256>>>(f1_w, x2_buf, n2_w, n2_b,
                                     f1_b, nullptr, nullptr, h1_buf, 4*CCH, CCH);

    // 7) out = x2 + g_ffn * (f2_w @ h1 + f2_b)   [M=256, K=1024]
    gemm_fused_kernel<0, true, false, true, false>
        <<<dim3(16, 4, BSZ), 256>>>(f2_w, h1_buf, nullptr, nullptr,
                                    f2_b, x2_buf, g_ff, out, CCH, 4*CCH);
}